// round 1
// baseline (speedup 1.0000x reference)
#include <cuda_runtime.h>
#include <math.h>

// ---------------- problem constants ----------------
#define BB   32
#define TW   40
#define T1   38      // after tconv1
#define T2T  36      // after tconv2
#define NN   50
#define CIN  2
#define HH   128
#define CO   64
#define EE   800
#define NSL  (BB*T1)        // 1216 slices for cheb
#define MCHEB (NSL*NN)      // 60800
#define MT2   (BB*NN*T2T)   // 57600

// ---------------- scratch (device globals; no allocation) ----------------
__device__ float g_T0 [NSL*NN*HH];
__device__ float g_Tx1[NSL*NN*HH];
__device__ float g_Tx2[NSL*NN*HH];
__device__ float g_G  [NSL*NN*HH];
__device__ float g_ew  [NSL*EE];
__device__ int   g_ecol[NSL*EE];
__device__ int   g_eoff[NSL*51];
__device__ float g_T2  [BB*T2T*NN*CO];
__device__ float g_Wcat[384*192];
__device__ float g_bnA[NN];
__device__ float g_bnC[NN];
__device__ float g_S[BB*3*3200];
__device__ float g_pooled[BB*128];

__device__ __forceinline__ float sigm(float x){ return 1.f/(1.f+__expf(-x)); }

// ---------------- K1: temporal gated conv 1 (Cin=2 -> H=128) ----------------
__global__ void tconv1_kernel(const float* __restrict__ X,
                              const float* __restrict__ w1, const float* __restrict__ b1,
                              const float* __restrict__ w2, const float* __restrict__ b2,
                              const float* __restrict__ w3, const float* __restrict__ b3)
{
    int s = blockIdx.x;            // 0..NSL-1  (s = b*T1 + t)
    int b = s / T1, t = s % T1;
    int h = threadIdx.x;           // 0..127
    float W1[6], W2[6], W3[6];
#pragma unroll
    for (int i = 0; i < 6; i++) {
        W1[i] = w1[i*128 + h];
        W2[i] = w2[i*128 + h];
        W3[i] = w3[i*128 + h];
    }
    float bb1 = b1[h], bb2 = b2[h], bb3 = b3[h];

    __shared__ float xs[3][NN*CIN];       // X[b, t+kt, n, c]
    for (int i = threadIdx.x; i < 3*NN*CIN; i += 128) {
        int kt = i / (NN*CIN), rem = i % (NN*CIN);
        xs[kt][rem] = X[((size_t)(b*TW + t + kt)*NN)*CIN + rem];
    }
    __syncthreads();

    float* out = g_T0 + ((size_t)s*NN)*HH + h;
    for (int n = 0; n < NN; n++) {
        float p = bb1, q = bb2, r = bb3;
#pragma unroll
        for (int kt = 0; kt < 3; kt++) {
#pragma unroll
            for (int c = 0; c < 2; c++) {
                float xv = xs[kt][n*2 + c];
                p += xv * W1[kt*2 + c];
                q += xv * W2[kt*2 + c];
                r += xv * W3[kt*2 + c];
            }
        }
        float v = p * sigm(q) + r;
        out[(size_t)n*HH] = v > 0.f ? v : 0.f;
    }
}

// -------- K2: edge weights + counting sort into per-slice CSR --------
__global__ void edge_prep_kernel(const int* __restrict__ ei)
{
    int s = blockIdx.x;
    int b = s / T1, t = s % T1;
    const int* row = ei + (size_t)(b*TW + t) * (2*EE);
    const int* col = row + EE;

    __shared__ int   deg[NN];
    __shared__ float dis[NN];
    __shared__ int   off[NN+1];
    __shared__ int   cur[NN];
    __shared__ int   rsh[EE];
    __shared__ int   csh[EE];

    for (int i = threadIdx.x; i < NN; i += blockDim.x) deg[i] = 0;
    __syncthreads();
    for (int e = threadIdx.x; e < EE; e += blockDim.x) {
        int r = row[e];
        rsh[e] = r; csh[e] = col[e];
        atomicAdd(&deg[r], 1);
    }
    __syncthreads();
    if (threadIdx.x == 0) {
        int acc = 0;
        for (int n = 0; n < NN; n++) { off[n] = acc; cur[n] = acc; acc += deg[n]; }
        off[NN] = acc;
    }
    for (int i = threadIdx.x; i < NN; i += blockDim.x)
        dis[i] = deg[i] > 0 ? rsqrtf((float)deg[i]) : 0.f;
    __syncthreads();
    for (int e = threadIdx.x; e < EE; e += blockDim.x) {
        int r = rsh[e], c = csh[e];
        int pos = atomicAdd(&cur[r], 1);
        g_ew  [(size_t)s*EE + pos] = -dis[r] * dis[c];
        g_ecol[(size_t)s*EE + pos] = c;
    }
    for (int i = threadIdx.x; i < NN+1; i += blockDim.x)
        g_eoff[s*(NN+1) + i] = off[i];
}

// -------- K3: cheb propagation (gather via CSR). mode 0: Tx1=L~T0. mode 1: Tx2=2*L~Tx1-T0 --------
__global__ void prop_kernel(int mode)
{
    int s = blockIdx.x;
    int f = threadIdx.x;  // 0..127
    const float* x   = (mode == 0) ? g_T0  : g_Tx1;
    float*       out = (mode == 0) ? g_Tx1 : g_Tx2;

    __shared__ float xs[NN*HH];
    __shared__ float ws[EE];
    __shared__ int   cs[EE];
    __shared__ int   offs[NN+1];

    const float* xsrc = x + (size_t)s*NN*HH;
    for (int i = threadIdx.x; i < NN*HH; i += blockDim.x) xs[i] = xsrc[i];
    for (int e = threadIdx.x; e < EE; e += blockDim.x) {
        ws[e] = g_ew  [(size_t)s*EE + e];
        cs[e] = g_ecol[(size_t)s*EE + e];
    }
    for (int i = threadIdx.x; i < NN+1; i += blockDim.x) offs[i] = g_eoff[s*(NN+1)+i];
    __syncthreads();

    for (int n = 0; n < NN; n++) {
        float acc = 0.f;
        int e0 = offs[n], e1 = offs[n+1];
        for (int e = e0; e < e1; e++)
            acc += ws[e] * xs[cs[e]*HH + f];
        size_t oi = ((size_t)s*NN + n)*HH + f;
        if (mode == 1) acc = 2.f*acc - g_T0[oi];
        out[oi] = acc;
    }
}

// -------- K4: cheb einsum GEMM: [T0|Tx1|Tx2](M x 384) @ cheb_w(384 x 128) + b, relu --------
__global__ void cheb_gemm_kernel(const float* __restrict__ W, const float* __restrict__ bias)
{
    int m0  = blockIdx.x * 64;
    int tid = threadIdx.x;          // 256
    int tx  = tid & 15, ty = tid >> 4;

    __shared__ float As[32][65];
    __shared__ float Bs[32][128];

    float acc[4][8];
#pragma unroll
    for (int i = 0; i < 4; i++)
#pragma unroll
        for (int j = 0; j < 8; j++) acc[i][j] = 0.f;

    for (int kc = 0; kc < 12; kc++) {
        const float* Am = (kc < 4) ? g_T0 : (kc < 8 ? g_Tx1 : g_Tx2);
        int f0 = (kc & 3) * 32;
#pragma unroll
        for (int i = 0; i < 8; i++) {
            int idx = tid + i*256;
            int m = idx >> 5, k = idx & 31;
            As[k][m] = Am[(size_t)(m0 + m)*HH + f0 + k];
        }
#pragma unroll
        for (int i = 0; i < 16; i++) {
            int idx = tid + i*256;
            int o = idx & 127, k = idx >> 7;
            Bs[k][o] = W[(kc*32 + k)*128 + o];
        }
        __syncthreads();
#pragma unroll
        for (int k = 0; k < 32; k++) {
            float a[4];
#pragma unroll
            for (int i = 0; i < 4; i++) a[i] = As[k][ty*4 + i];
            float4 b0 = *reinterpret_cast<const float4*>(&Bs[k][tx*8]);
            float4 b1 = *reinterpret_cast<const float4*>(&Bs[k][tx*8 + 4]);
            float bq[8] = {b0.x,b0.y,b0.z,b0.w,b1.x,b1.y,b1.z,b1.w};
#pragma unroll
            for (int i = 0; i < 4; i++)
#pragma unroll
                for (int j = 0; j < 8; j++) acc[i][j] += a[i]*bq[j];
        }
        __syncthreads();
    }
#pragma unroll
    for (int i = 0; i < 4; i++) {
        int m = m0 + ty*4 + i;
        float r[8];
#pragma unroll
        for (int j = 0; j < 8; j++) {
            float v = acc[i][j] + bias[tx*8 + j];
            r[j] = v > 0.f ? v : 0.f;
        }
        float4* dst = reinterpret_cast<float4*>(&g_G[(size_t)m*HH + tx*8]);
        dst[0] = make_float4(r[0],r[1],r[2],r[3]);
        dst[1] = make_float4(r[4],r[5],r[6],r[7]);
    }
}

// -------- K5a: interleave the three tconv2 weight matrices: Wcat[kk][co*3+v] --------
__global__ void build_wcat_kernel(const float* __restrict__ w1,
                                  const float* __restrict__ w2,
                                  const float* __restrict__ w3)
{
    int idx = blockIdx.x*256 + threadIdx.x;
    if (idx >= 384*192) return;
    int jj = idx % 192, kk = idx / 192;
    int co = jj / 3, v = jj % 3;
    const float* w = (v == 0) ? w1 : (v == 1 ? w2 : w3);
    g_Wcat[idx] = w[kk*CO + co];     // w layout (kt,h,co) flat == kk*64+co
}

// -------- K5: tconv2 GEMM (M=57600, K=384, N=192) + gated epilogue --------
__global__ void tconv2_gemm_kernel(const float* __restrict__ b1,
                                   const float* __restrict__ b2,
                                   const float* __restrict__ b3)
{
    int m0  = blockIdx.x * 64;
    int tid = threadIdx.x;
    int tx  = tid & 15, ty = tid >> 4;

    __shared__ float As[32][65];
    __shared__ float Bs[32][192];

    float acc[4][12];
#pragma unroll
    for (int i = 0; i < 4; i++)
#pragma unroll
        for (int j = 0; j < 12; j++) acc[i][j] = 0.f;

    for (int kc = 0; kc < 12; kc++) {
        int kt = kc >> 2;
        int h0 = (kc & 3) * 32;
#pragma unroll
        for (int i = 0; i < 8; i++) {
            int idx = tid + i*256;
            int m = idx >> 5, k = idx & 31;
            int gm = m0 + m;                   // gm = (b*50+n)*36 + t
            int t = gm % 36, n = (gm/36) % 50, b = gm / 1800;
            As[k][m] = g_G[(((size_t)(b*T1 + t + kt))*NN + n)*HH + h0 + k];
        }
#pragma unroll
        for (int i = 0; i < 24; i++) {
            int idx = tid + i*256;
            int jj = idx % 192, k = idx / 192;
            Bs[k][jj] = g_Wcat[(kc*32 + k)*192 + jj];
        }
        __syncthreads();
#pragma unroll
        for (int k = 0; k < 32; k++) {
            float a[4];
#pragma unroll
            for (int i = 0; i < 4; i++) a[i] = As[k][ty*4 + i];
            float4 v0 = *reinterpret_cast<const float4*>(&Bs[k][tx*12]);
            float4 v1 = *reinterpret_cast<const float4*>(&Bs[k][tx*12 + 4]);
            float4 v2 = *reinterpret_cast<const float4*>(&Bs[k][tx*12 + 8]);
            float bq[12] = {v0.x,v0.y,v0.z,v0.w,v1.x,v1.y,v1.z,v1.w,v2.x,v2.y,v2.z,v2.w};
#pragma unroll
            for (int i = 0; i < 4; i++)
#pragma unroll
                for (int j = 0; j < 12; j++) acc[i][j] += a[i]*bq[j];
        }
        __syncthreads();
    }
    // epilogue: jj = co*3 + {P,Q,R}; this thread owns co = tx*4 .. tx*4+3
#pragma unroll
    for (int i = 0; i < 4; i++) {
        int gm = m0 + ty*4 + i;
        int t = gm % 36, n = (gm/36) % 50, b = gm / 1800;
        float r[4];
#pragma unroll
        for (int cq = 0; cq < 4; cq++) {
            int co = tx*4 + cq;
            float p = acc[i][cq*3 + 0] + b1[co];
            float q = acc[i][cq*3 + 1] + b2[co];
            float rr= acc[i][cq*3 + 2] + b3[co];
            float v = p * sigm(q) + rr;
            r[cq] = v > 0.f ? v : 0.f;
        }
        float4* dst = reinterpret_cast<float4*>(
            &g_T2[(((size_t)(b*T2T + t))*NN + n)*CO + tx*4]);
        dst[0] = make_float4(r[0],r[1],r[2],r[3]);
    }
}

// -------- K6: BatchNorm stats per node n --------
__global__ void bn_stats_kernel(const float* __restrict__ gamma,
                                const float* __restrict__ beta)
{
    int n = blockIdx.x;
    int tid = threadIdx.x;
    double s = 0.0, s2 = 0.0;
    const int M = BB*T2T*CO;   // 73728
    for (int i = tid; i < M; i += blockDim.x) {
        int bt = i >> 6, co = i & 63;
        float v = g_T2[((size_t)bt*NN + n)*CO + co];
        s  += v;
        s2 += (double)v * v;
    }
    __shared__ double shs[256], shs2[256];
    shs[tid] = s; shs2[tid] = s2;
    __syncthreads();
    for (int stp = 128; stp > 0; stp >>= 1) {
        if (tid < stp) { shs[tid] += shs[tid+stp]; shs2[tid] += shs2[tid+stp]; }
        __syncthreads();
    }
    if (tid == 0) {
        double mean = shs[0] / (double)M;
        double var  = shs2[0] / (double)M - mean*mean;
        float  rstd = (float)(1.0 / sqrt(var + 1e-5));
        float  a = rstd * gamma[n];
        g_bnA[n] = a;
        g_bnC[n] = beta[n] - (float)mean * a;
    }
}

// -------- K7: window sums over t (conv3 mean-pool commuted) with BN folded in --------
__global__ void swin_kernel()
{
    int b = blockIdx.x;
    int j = blockIdx.y*128 + threadIdx.x;   // 0..3199  (= n*64+co)
    const float* base = g_T2 + (size_t)b*T2T*3200 + j;
    float tot = 0.f, v0 = 0.f, v1 = 0.f, v34 = 0.f, v35 = 0.f;
#pragma unroll
    for (int t = 0; t < T2T; t++) {
        float v = base[(size_t)t*3200];
        tot += v;
        if (t == 0)  v0  = v;
        if (t == 1)  v1  = v;
        if (t == 34) v34 = v;
        if (t == 35) v35 = v;
    }
    int n = j >> 6;
    float a = g_bnA[n], c = 34.f * g_bnC[n];
    g_S[((size_t)b*3 + 0)*3200 + j] = a*(tot - v34 - v35) + c;   // t window [0,34)
    g_S[((size_t)b*3 + 1)*3200 + j] = a*(tot - v0  - v35) + c;   // [1,35)
    g_S[((size_t)b*3 + 2)*3200 + j] = a*(tot - v0  - v1 ) + c;   // [2,36)
}

// -------- K8: pooled[b,o] = (sum_{kt,j} conv3_w[o,kt,j]*S[b,kt,j])/34 + conv3_b[o] --------
__global__ void pooled_kernel(const float* __restrict__ w,
                              const float* __restrict__ cb)
{
    int b  = blockIdx.x;
    int og = blockIdx.y;         // 8 groups of 16 outputs
    __shared__ float sS[9600];
    for (int i = threadIdx.x; i < 9600; i += 256)
        sS[i] = g_S[(size_t)b*9600 + i];
    __syncthreads();
    int warp = threadIdx.x >> 5, lane = threadIdx.x & 31;
    for (int oi = warp; oi < 16; oi += 8) {
        int o = og*16 + oi;
        const float* wr = w + (size_t)o*9600;
        float acc = 0.f;
        for (int jj = lane; jj < 9600; jj += 32)
            acc += wr[jj] * sS[jj];
#pragma unroll
        for (int d = 16; d > 0; d >>= 1)
            acc += __shfl_down_sync(0xffffffffu, acc, d);
        if (lane == 0)
            g_pooled[b*128 + o] = acc * (1.f/34.f) + cb[o];
    }
}

// -------- K9: out = pooled @ f1_w + f1_b --------
__global__ void fc_kernel(const float* __restrict__ f1w,
                          const float* __restrict__ f1b,
                          float* __restrict__ out)
{
    int b = blockIdx.x;
    int q = blockIdx.y*128 + threadIdx.x;
    __shared__ float p[128];
    p[threadIdx.x] = g_pooled[b*128 + threadIdx.x];
    __syncthreads();
    float acc = f1b[q];
#pragma unroll 8
    for (int o = 0; o < 128; o++)
        acc += p[o] * f1w[(size_t)o*3200 + q];
    out[(size_t)b*3200 + q] = acc;
}

// ---------------- launch ----------------
extern "C" void kernel_launch(void* const* d_in, const int* in_sizes, int n_in,
                              void* d_out, int out_size)
{
    // input index mapping: setup_inputs dict order puts edge_index at [1] (2,048,000 elems);
    // python signature order puts tc1_w1 at [1] (768 elems). Detect at runtime.
    int iEI, iT1W1, iT1B1, iT1W2, iT1B2, iT1W3, iT1B3, iCW, iCB;
    int iT2W1, iT2B1, iT2W2, iT2B2, iT2W3, iT2B3, iGam, iBet, iC3W, iC3B, iF1W, iF1B;
    if (n_in > 1 && in_sizes[1] == BB*TW*2*EE) {
        iEI=1;  iT1W1=2;  iT1B1=3;  iT1W2=4;  iT1B2=5;  iT1W3=6;  iT1B3=7;
        iCW=8;  iCB=9;
        iT2W1=10; iT2B1=11; iT2W2=12; iT2B2=13; iT2W3=14; iT2B3=15;
        iGam=16; iBet=17; iC3W=18; iC3B=19; iF1W=20; iF1B=21;
    } else {
        iT1W1=1;  iT1B1=2;  iT1W2=3;  iT1B2=4;  iT1W3=5;  iT1B3=6;
        iCW=7;  iCB=8;
        iT2W1=9;  iT2B1=10; iT2W2=11; iT2B2=12; iT2W3=13; iT2B3=14;
        iGam=15; iBet=16; iC3W=17; iC3B=18; iF1W=19; iF1B=20; iEI=21;
    }

    const float* X    = (const float*)d_in[0];
    const int*   EI   = (const int*)  d_in[iEI];
    const float* t1w1 = (const float*)d_in[iT1W1];
    const float* t1b1 = (const float*)d_in[iT1B1];
    const float* t1w2 = (const float*)d_in[iT1W2];
    const float* t1b2 = (const float*)d_in[iT1B2];
    const float* t1w3 = (const float*)d_in[iT1W3];
    const float* t1b3 = (const float*)d_in[iT1B3];
    const float* chw  = (const float*)d_in[iCW];
    const float* chb  = (const float*)d_in[iCB];
    const float* t2w1 = (const float*)d_in[iT2W1];
    const float* t2b1 = (const float*)d_in[iT2B1];
    const float* t2w2 = (const float*)d_in[iT2W2];
    const float* t2b2 = (const float*)d_in[iT2B2];
    const float* t2w3 = (const float*)d_in[iT2W3];
    const float* t2b3 = (const float*)d_in[iT2B3];
    const float* gam  = (const float*)d_in[iGam];
    const float* bet  = (const float*)d_in[iBet];
    const float* c3w  = (const float*)d_in[iC3W];
    const float* c3b  = (const float*)d_in[iC3B];
    const float* f1w  = (const float*)d_in[iF1W];
    const float* f1b  = (const float*)d_in[iF1B];
    float* out = (float*)d_out;

    tconv1_kernel<<<NSL, 128>>>(X, t1w1, t1b1, t1w2, t1b2, t1w3, t1b3);
    edge_prep_kernel<<<NSL, 256>>>(EI);
    prop_kernel<<<NSL, 128>>>(0);
    prop_kernel<<<NSL, 128>>>(1);
    cheb_gemm_kernel<<<MCHEB/64, 256>>>(chw, chb);
    build_wcat_kernel<<<(384*192 + 255)/256, 256>>>(t2w1, t2w2, t2w3);
    tconv2_gemm_kernel<<<MT2/64, 256>>>(t2b1, t2b2, t2b3);
    bn_stats_kernel<<<NN, 256>>>(gam, bet);
    swin_kernel<<<dim3(BB, 25), 128>>>();
    pooled_kernel<<<dim3(BB, 8), 256>>>(c3w, c3b);
    fc_kernel<<<dim3(BB, 25), 128>>>(f1w, f1b, out);
}

// round 4
// speedup vs baseline: 1.8707x; 1.8707x over previous
#include <cuda_runtime.h>
#include <cuda_bf16.h>
#include <math.h>
#include <stdint.h>

// ---------------- problem constants ----------------
#define BB   32
#define TW   40
#define T1   38
#define T2T  36
#define NN   50
#define CIN  2
#define HH   128
#define CO   64
#define EE   800
#define NSL  (BB*T1)        // 1216
#define MCHEB (NSL*NN)      // 60800
#define MT2   (BB*NN*T2T)   // 57600

// ---------------- scratch ----------------
__device__ float g_T0  [(size_t)NSL*NN*HH];   // exact fp32 (prop input)
__device__ float g_T0r [(size_t)NSL*NN*HH];   // tf32-rounded GEMM operand
__device__ float g_Tx1r[(size_t)NSL*NN*HH];
__device__ float g_Tx2r[(size_t)NSL*NN*HH];
__device__ float g_Gr  [(size_t)NSL*NN*HH];   // relu(cheb out), tf32-rounded
__device__ float g_ew  [NSL*EE];
__device__ int   g_ecol[NSL*EE];              // col * HH (pre-scaled)
__device__ int   g_eoff[NSL*51];
__device__ float g_T2  [BB*T2T*NN*CO];
__device__ float g_WchebT[128*384];           // [n][k], tf32-rounded
__device__ float g_WcatT [192*384];           // [j][k], j=v*64+co, tf32-rounded
__device__ float g_bnA[NN];
__device__ float g_bnC[NN];
__device__ float g_S[BB*3*3200];
__device__ float g_pooled[BB*128];

__device__ __forceinline__ float sigm(float x){ return 1.f/(1.f+__expf(-x)); }
__device__ __forceinline__ float tf32r(float x){
    uint32_t r; asm("cvt.rna.tf32.f32 %0, %1;" : "=r"(r) : "f"(x));
    return __uint_as_float(r);
}

// ---------------- PTX helpers (sm_103 baseline only) ----------------
__device__ __forceinline__ uint32_t smem_u32(const void* p){
    uint32_t a;
    asm("{ .reg .u64 t; cvta.to.shared.u64 t, %1; cvt.u32.u64 %0, t; }" : "=r"(a) : "l"(p));
    return a;
}
__device__ __forceinline__ uint32_t swz128(uint32_t off){ return off ^ ((off >> 3) & 0x70); }
__device__ __forceinline__ void cp16(uint32_t dst, const void* src){
    asm volatile("cp.async.cg.shared.global [%0], [%1], 16;" :: "r"(dst), "l"(src));
}
__device__ __forceinline__ void cp_commit_wait(){
    asm volatile("cp.async.commit_group;");
    asm volatile("cp.async.wait_group 0;");
}
__device__ __forceinline__ void mma_tf32(float* c, const uint32_t* a, const uint32_t* b){
    asm volatile("mma.sync.aligned.m16n8k8.row.col.f32.tf32.tf32.f32 "
        "{%0,%1,%2,%3}, {%4,%5,%6,%7}, {%8,%9}, {%0,%1,%2,%3};"
        : "+f"(c[0]), "+f"(c[1]), "+f"(c[2]), "+f"(c[3])
        : "r"(a[0]),"r"(a[1]),"r"(a[2]),"r"(a[3]), "r"(b[0]),"r"(b[1]));
}
// swizzled word index for a [rows][32-float] tile (128B rows)
__device__ __forceinline__ uint32_t swzw(int row, int k){
    return swz128((uint32_t)(row*128 + k*4)) >> 2;
}

// ---------------- K1: temporal gated conv 1 ----------------
__global__ void tconv1_kernel(const float* __restrict__ X,
                              const float* __restrict__ w1, const float* __restrict__ b1,
                              const float* __restrict__ w2, const float* __restrict__ b2,
                              const float* __restrict__ w3, const float* __restrict__ b3)
{
    int s = blockIdx.x;
    int b = s / T1, t = s % T1;
    int h = threadIdx.x;
    float W1[6], W2[6], W3[6];
#pragma unroll
    for (int i = 0; i < 6; i++) {
        W1[i] = w1[i*128 + h]; W2[i] = w2[i*128 + h]; W3[i] = w3[i*128 + h];
    }
    float bb1 = b1[h], bb2 = b2[h], bb3 = b3[h];

    __shared__ float xs[3][NN*CIN];
    for (int i = threadIdx.x; i < 3*NN*CIN; i += 128) {
        int kt = i / (NN*CIN), rem = i % (NN*CIN);
        xs[kt][rem] = X[((size_t)(b*TW + t + kt)*NN)*CIN + rem];
    }
    __syncthreads();

    size_t ob = ((size_t)s*NN)*HH + h;
    for (int n = 0; n < NN; n++) {
        float p = bb1, q = bb2, r = bb3;
#pragma unroll
        for (int kt = 0; kt < 3; kt++)
#pragma unroll
            for (int c = 0; c < 2; c++) {
                float xv = xs[kt][n*2 + c];
                p += xv * W1[kt*2 + c]; q += xv * W2[kt*2 + c]; r += xv * W3[kt*2 + c];
            }
        float v = p * sigm(q) + r;
        v = v > 0.f ? v : 0.f;
        g_T0 [ob + (size_t)n*HH] = v;
        g_T0r[ob + (size_t)n*HH] = tf32r(v);
    }
}

// -------- K2: edge prep (CSR counting sort; col pre-scaled by HH) --------
__global__ void edge_prep_kernel(const int* __restrict__ ei)
{
    int s = blockIdx.x;
    int b = s / T1, t = s % T1;
    const int* row = ei + (size_t)(b*TW + t) * (2*EE);
    const int* col = row + EE;

    __shared__ int   deg[NN];
    __shared__ float dis[NN];
    __shared__ int   off[NN+1];
    __shared__ int   cur[NN];
    __shared__ int   rsh[EE];
    __shared__ int   csh[EE];

    for (int i = threadIdx.x; i < NN; i += blockDim.x) deg[i] = 0;
    __syncthreads();
    for (int e = threadIdx.x; e < EE; e += blockDim.x) {
        int r = row[e];
        rsh[e] = r; csh[e] = col[e];
        atomicAdd(&deg[r], 1);
    }
    __syncthreads();
    if (threadIdx.x == 0) {
        int acc = 0;
        for (int n = 0; n < NN; n++) { off[n] = acc; cur[n] = acc; acc += deg[n]; }
        off[NN] = acc;
    }
    for (int i = threadIdx.x; i < NN; i += blockDim.x)
        dis[i] = deg[i] > 0 ? rsqrtf((float)deg[i]) : 0.f;
    __syncthreads();
    for (int e = threadIdx.x; e < EE; e += blockDim.x) {
        int r = rsh[e], c = csh[e];
        int pos = atomicAdd(&cur[r], 1);
        g_ew  [(size_t)s*EE + pos] = -dis[r] * dis[c];
        g_ecol[(size_t)s*EE + pos] = c * HH;
    }
    for (int i = threadIdx.x; i < NN+1; i += blockDim.x)
        g_eoff[s*(NN+1) + i] = off[i];
}

// -------- K3: fused Chebyshev propagation --------
__global__ void prop_fused_kernel()
{
    extern __shared__ float dyn[];
    float* xs = dyn;
    float* xt = dyn + NN*HH;
    float* ws = dyn + 2*NN*HH;
    int*   cs = (int*)(dyn + 2*NN*HH + EE);
    int* offs = (int*)(dyn + 2*NN*HH + 2*EE);

    int s = blockIdx.x;
    int tid = threadIdx.x;           // 256
    int f = tid & 127;
    int half = tid >> 7;

    const float* xsrc = g_T0 + (size_t)s*NN*HH;
    for (int i = tid; i < NN*HH; i += 256) xs[i] = xsrc[i];
    for (int e = tid; e < EE; e += 256) {
        ws[e] = g_ew  [(size_t)s*EE + e];
        cs[e] = g_ecol[(size_t)s*EE + e];
    }
    for (int i = tid; i < NN+1; i += 256) offs[i] = g_eoff[s*(NN+1)+i];
    __syncthreads();

    int n0 = half*25, n1 = n0 + 25;
    for (int n = n0; n < n1; n++) {
        int e0 = offs[n], e1 = offs[n+1];
        float a0=0.f, a1=0.f, a2=0.f, a3=0.f;
        int e = e0;
        for (; e + 3 < e1; e += 4) {
            a0 += ws[e  ] * xs[cs[e  ] + f];
            a1 += ws[e+1] * xs[cs[e+1] + f];
            a2 += ws[e+2] * xs[cs[e+2] + f];
            a3 += ws[e+3] * xs[cs[e+3] + f];
        }
        for (; e < e1; e++) a0 += ws[e] * xs[cs[e] + f];
        float acc = (a0 + a1) + (a2 + a3);
        xt[n*HH + f] = acc;
        g_Tx1r[((size_t)s*NN + n)*HH + f] = tf32r(acc);
    }
    __syncthreads();
    for (int n = n0; n < n1; n++) {
        int e0 = offs[n], e1 = offs[n+1];
        float a0=0.f, a1=0.f, a2=0.f, a3=0.f;
        int e = e0;
        for (; e + 3 < e1; e += 4) {
            a0 += ws[e  ] * xt[cs[e  ] + f];
            a1 += ws[e+1] * xt[cs[e+1] + f];
            a2 += ws[e+2] * xt[cs[e+2] + f];
            a3 += ws[e+3] * xt[cs[e+3] + f];
        }
        for (; e < e1; e++) a0 += ws[e] * xt[cs[e] + f];
        float acc = 2.f*((a0 + a1) + (a2 + a3)) - xs[n*HH + f];
        g_Tx2r[((size_t)s*NN + n)*HH + f] = tf32r(acc);
    }
}

// -------- K3b: weight prep (transpose + tf32 round) --------
__global__ void prep_w_kernel(const float* __restrict__ chw,
                              const float* __restrict__ w1,
                              const float* __restrict__ w2,
                              const float* __restrict__ w3)
{
    int idx = blockIdx.x*256 + threadIdx.x;
    if (idx < 128*384) {
        int n = idx / 384, k = idx % 384;
        g_WchebT[idx] = tf32r(chw[k*128 + n]);
    }
    if (idx < 192*384) {
        int j = idx / 384, k = idx % 384;
        int v = j >> 6, co = j & 63;
        const float* w = (v == 0) ? w1 : (v == 1 ? w2 : w3);
        g_WcatT[idx] = tf32r(w[k*64 + co]);
    }
}

// -------- K4: cheb einsum GEMM via tf32 mma.sync (M=60800, N=128, K=384) --------
__global__ __launch_bounds__(256, 1)
void cheb_mma_kernel(const float* __restrict__ bias)
{
    __shared__ __align__(1024) float sA[128*32];
    __shared__ __align__(1024) float sB[128*32];

    int tid = threadIdx.x;
    int wid = tid >> 5, lane = tid & 31;
    int wm = (wid >> 2) * 64;        // 2 m-warps
    int wn = (wid & 3) * 32;         // 4 n-warps
    uint32_t sa = smem_u32(sA), sb = smem_u32(sB);
    const uint32_t* sAu = (const uint32_t*)sA;
    const uint32_t* sBu = (const uint32_t*)sB;
    size_t m0 = (size_t)blockIdx.x * 128;

    float acc[4][4][4];
#pragma unroll
    for (int i = 0; i < 4; i++)
#pragma unroll
        for (int j = 0; j < 4; j++)
#pragma unroll
            for (int r = 0; r < 4; r++) acc[i][j][r] = 0.f;

    for (int c = 0; c < 12; c++) {
        const float* Am = (c < 4) ? g_T0r : (c < 8 ? g_Tx1r : g_Tx2r);
        int k0 = (c & 3) * 32;
#pragma unroll
        for (int i = 0; i < 4; i++) {                  // A: 1024 16B units
            int u = tid + i*256;
            int row = u >> 3, un = u & 7;
            cp16(sa + swz128((uint32_t)(row*128 + un*16)),
                 Am + (m0 + row)*HH + k0 + un*4);
        }
#pragma unroll
        for (int i = 0; i < 4; i++) {                  // B: 1024 16B units
            int u = tid + i*256;
            int row = u >> 3, un = u & 7;
            cp16(sb + swz128((uint32_t)(row*128 + un*16)),
                 g_WchebT + (size_t)row*384 + c*32 + un*4);
        }
        cp_commit_wait();
        __syncthreads();

#pragma unroll
        for (int k8 = 0; k8 < 4; k8++) {
            int kb = k8*8 + (lane & 3);
            uint32_t a[4][4], b[4][2];
#pragma unroll
            for (int mf = 0; mf < 4; mf++) {
                int r0 = wm + mf*16 + (lane >> 2);
                a[mf][0] = sAu[swzw(r0,     kb)];
                a[mf][1] = sAu[swzw(r0 + 8, kb)];
                a[mf][2] = sAu[swzw(r0,     kb + 4)];
                a[mf][3] = sAu[swzw(r0 + 8, kb + 4)];
            }
#pragma unroll
            for (int nf = 0; nf < 4; nf++) {
                int n0 = wn + nf*8 + (lane >> 2);
                b[nf][0] = sBu[swzw(n0, kb)];
                b[nf][1] = sBu[swzw(n0, kb + 4)];
            }
#pragma unroll
            for (int mf = 0; mf < 4; mf++)
#pragma unroll
                for (int nf = 0; nf < 4; nf++)
                    mma_tf32(acc[mf][nf], a[mf], b[nf]);
        }
        __syncthreads();
    }

    // epilogue: + bias, relu, tf32-round, store fp32
    int rl = lane >> 2, cl = (lane & 3)*2;
#pragma unroll
    for (int mf = 0; mf < 4; mf++) {
        size_t mrow = m0 + wm + mf*16 + rl;
#pragma unroll
        for (int nf = 0; nf < 4; nf++) {
            int n = wn + nf*8 + cl;
            float bv0 = bias[n], bv1 = bias[n+1];
            float v00 = acc[mf][nf][0] + bv0; v00 = v00 > 0.f ? v00 : 0.f;
            float v01 = acc[mf][nf][1] + bv1; v01 = v01 > 0.f ? v01 : 0.f;
            float v10 = acc[mf][nf][2] + bv0; v10 = v10 > 0.f ? v10 : 0.f;
            float v11 = acc[mf][nf][3] + bv1; v11 = v11 > 0.f ? v11 : 0.f;
            *reinterpret_cast<float2*>(&g_Gr[mrow*HH + n]) =
                make_float2(tf32r(v00), tf32r(v01));
            *reinterpret_cast<float2*>(&g_Gr[(mrow+8)*HH + n]) =
                make_float2(tf32r(v10), tf32r(v11));
        }
    }
}

// -------- K5: tconv2 GEMM via tf32 mma.sync (M=57600, N=192, K=384) + gating --------
__global__ __launch_bounds__(256, 1)
void tconv2_mma_kernel(const float* __restrict__ b1,
                       const float* __restrict__ b2,
                       const float* __restrict__ b3)
{
    __shared__ __align__(1024) float sA[128*32];
    __shared__ __align__(1024) float sB[192*32];

    int tid = threadIdx.x;
    int wid = tid >> 5, lane = tid & 31;
    int wm = (wid >> 2) * 64;
    int cg = wid & 3;                 // 16-wide co group
    uint32_t sa = smem_u32(sA), sb = smem_u32(sB);
    const uint32_t* sAu = (const uint32_t*)sA;
    const uint32_t* sBu = (const uint32_t*)sB;
    int m0 = blockIdx.x * 128;

    float acc[4][3][2][4];
#pragma unroll
    for (int i = 0; i < 4; i++)
#pragma unroll
        for (int v = 0; v < 3; v++)
#pragma unroll
            for (int cf = 0; cf < 2; cf++)
#pragma unroll
                for (int r = 0; r < 4; r++) acc[i][v][cf][r] = 0.f;

    for (int c = 0; c < 12; c++) {
        int kt = c >> 2;
        int k0 = (c & 3) * 32;
#pragma unroll
        for (int i = 0; i < 4; i++) {                  // A gather: 1024 units
            int u = tid + i*256;
            int row = u >> 3, un = u & 7;
            int gm = m0 + row;
            int t = gm % 36, n = (gm/36) % 50, b = gm / 1800;
            cp16(sa + swz128((uint32_t)(row*128 + un*16)),
                 g_Gr + (((size_t)(b*T1 + t + kt))*NN + n)*HH + k0 + un*4);
        }
#pragma unroll
        for (int i = 0; i < 6; i++) {                  // B: 1536 units
            int u = tid + i*256;
            int row = u >> 3, un = u & 7;
            cp16(sb + swz128((uint32_t)(row*128 + un*16)),
                 g_WcatT + (size_t)row*384 + c*32 + un*4);
        }
        cp_commit_wait();
        __syncthreads();

#pragma unroll
        for (int k8 = 0; k8 < 4; k8++) {
            int kb = k8*8 + (lane & 3);
            uint32_t a[4][4], b[6][2];
#pragma unroll
            for (int mf = 0; mf < 4; mf++) {
                int r0 = wm + mf*16 + (lane >> 2);
                a[mf][0] = sAu[swzw(r0,     kb)];
                a[mf][1] = sAu[swzw(r0 + 8, kb)];
                a[mf][2] = sAu[swzw(r0,     kb + 4)];
                a[mf][3] = sAu[swzw(r0 + 8, kb + 4)];
            }
#pragma unroll
            for (int v = 0; v < 3; v++)
#pragma unroll
                for (int cf = 0; cf < 2; cf++) {
                    int nrow = v*64 + cg*16 + cf*8 + (lane >> 2);
                    b[v*2+cf][0] = sBu[swzw(nrow, kb)];
                    b[v*2+cf][1] = sBu[swzw(nrow, kb + 4)];
                }
#pragma unroll
            for (int mf = 0; mf < 4; mf++)
#pragma unroll
                for (int v = 0; v < 3; v++)
#pragma unroll
                    for (int cf = 0; cf < 2; cf++)
                        mma_tf32(acc[mf][v][cf], a[mf], b[v*2+cf]);
        }
        __syncthreads();
    }

    // epilogue: gated P*sigm(Q)+R, relu -> g_T2 fp32
    int rl = lane >> 2, cl = (lane & 3)*2;
#pragma unroll
    for (int mf = 0; mf < 4; mf++) {
#pragma unroll
        for (int h = 0; h < 2; h++) {
            int gm = m0 + wm + mf*16 + rl + h*8;
            int t = gm % 36, n = (gm/36) % 50, b = gm / 1800;
            float* dst = g_T2 + (((size_t)(b*T2T + t))*NN + n)*CO;
#pragma unroll
            for (int cf = 0; cf < 2; cf++) {
                int co = cg*16 + cf*8 + cl;
                float p0 = acc[mf][0][cf][h*2+0] + b1[co];
                float p1 = acc[mf][0][cf][h*2+1] + b1[co+1];
                float q0 = acc[mf][1][cf][h*2+0] + b2[co];
                float q1 = acc[mf][1][cf][h*2+1] + b2[co+1];
                float r0 = acc[mf][2][cf][h*2+0] + b3[co];
                float r1 = acc[mf][2][cf][h*2+1] + b3[co+1];
                float v0 = p0 * sigm(q0) + r0; v0 = v0 > 0.f ? v0 : 0.f;
                float v1 = p1 * sigm(q1) + r1; v1 = v1 > 0.f ? v1 : 0.f;
                *reinterpret_cast<float2*>(dst + co) = make_float2(v0, v1);
            }
        }
    }
}

// -------- K6: BatchNorm stats per node n --------
__global__ void bn_stats_kernel(const float* __restrict__ gamma,
                                const float* __restrict__ beta)
{
    int n = blockIdx.x;
    int tid = threadIdx.x;
    double s = 0.0, s2 = 0.0;
    const int M = BB*T2T*CO;
    for (int i = tid; i < M; i += blockDim.x) {
        int bt = i >> 6, co = i & 63;
        float v = g_T2[((size_t)bt*NN + n)*CO + co];
        s += v; s2 += (double)v * v;
    }
    __shared__ double shs[256], shs2[256];
    shs[tid] = s; shs2[tid] = s2;
    __syncthreads();
    for (int stp = 128; stp > 0; stp >>= 1) {
        if (tid < stp) { shs[tid] += shs[tid+stp]; shs2[tid] += shs2[tid+stp]; }
        __syncthreads();
    }
    if (tid == 0) {
        double mean = shs[0] / (double)M;
        double var  = shs2[0] / (double)M - mean*mean;
        float  rstd = (float)(1.0 / sqrt(var + 1e-5));
        float  a = rstd * gamma[n];
        g_bnA[n] = a;
        g_bnC[n] = beta[n] - (float)mean * a;
    }
}

// -------- K7: window sums with BN folded --------
__global__ void swin_kernel()
{
    int b = blockIdx.x;
    int j = blockIdx.y*128 + threadIdx.x;
    const float* base = g_T2 + (size_t)b*T2T*3200 + j;
    float tot = 0.f, v0 = 0.f, v1 = 0.f, v34 = 0.f, v35 = 0.f;
#pragma unroll
    for (int t = 0; t < T2T; t++) {
        float v = base[(size_t)t*3200];
        tot += v;
        if (t == 0)  v0  = v;
        if (t == 1)  v1  = v;
        if (t == 34) v34 = v;
        if (t == 35) v35 = v;
    }
    int n = j >> 6;
    float a = g_bnA[n], c = 34.f * g_bnC[n];
    g_S[((size_t)b*3 + 0)*3200 + j] = a*(tot - v34 - v35) + c;
    g_S[((size_t)b*3 + 1)*3200 + j] = a*(tot - v0  - v35) + c;
    g_S[((size_t)b*3 + 2)*3200 + j] = a*(tot - v0  - v1 ) + c;
}

// -------- K8: pooled --------
__global__ void pooled_kernel(const float* __restrict__ w,
                              const float* __restrict__ cb)
{
    int b  = blockIdx.x;
    int og = blockIdx.y;
    __shared__ float sS[9600];
    for (int i = threadIdx.x; i < 9600; i += 256)
        sS[i] = g_S[(size_t)b*9600 + i];
    __syncthreads();
    int warp = threadIdx.x >> 5, lane = threadIdx.x & 31;
    for (int oi = warp; oi < 16; oi += 8) {
        int o = og*16 + oi;
        const float* wr = w + (size_t)o*9600;
        float acc = 0.f;
        for (int jj = lane; jj < 9600; jj += 32)
            acc += wr[jj] * sS[jj];
#pragma unroll
        for (int d = 16; d > 0; d >>= 1)
            acc += __shfl_down_sync(0xffffffffu, acc, d);
        if (lane == 0)
            g_pooled[b*128 + o] = acc * (1.f/34.f) + cb[o];
    }
}

// -------- K9: fc --------
__global__ void fc_kernel(const float* __restrict__ f1w,
                          const float* __restrict__ f1b,
                          float* __restrict__ out)
{
    int b = blockIdx.x;
    int q = blockIdx.y*128 + threadIdx.x;
    __shared__ float p[128];
    p[threadIdx.x] = g_pooled[b*128 + threadIdx.x];
    __syncthreads();
    float acc = f1b[q];
#pragma unroll 8
    for (int o = 0; o < 128; o++)
        acc += p[o] * f1w[(size_t)o*3200 + q];
    out[(size_t)b*3200 + q] = acc;
}

// ---------------- launch ----------------
extern "C" void kernel_launch(void* const* d_in, const int* in_sizes, int n_in,
                              void* d_out, int out_size)
{
    int iEI, iT1W1, iT1B1, iT1W2, iT1B2, iT1W3, iT1B3, iCW, iCB;
    int iT2W1, iT2B1, iT2W2, iT2B2, iT2W3, iT2B3, iGam, iBet, iC3W, iC3B, iF1W, iF1B;
    if (n_in > 1 && in_sizes[1] == BB*TW*2*EE) {
        iEI=1;  iT1W1=2;  iT1B1=3;  iT1W2=4;  iT1B2=5;  iT1W3=6;  iT1B3=7;
        iCW=8;  iCB=9;
        iT2W1=10; iT2B1=11; iT2W2=12; iT2B2=13; iT2W3=14; iT2B3=15;
        iGam=16; iBet=17; iC3W=18; iC3B=19; iF1W=20; iF1B=21;
    } else {
        iT1W1=1;  iT1B1=2;  iT1W2=3;  iT1B2=4;  iT1W3=5;  iT1B3=6;
        iCW=7;  iCB=8;
        iT2W1=9;  iT2B1=10; iT2W2=11; iT2B2=12; iT2W3=13; iT2B3=14;
        iGam=15; iBet=16; iC3W=17; iC3B=18; iF1W=19; iF1B=20; iEI=21;
    }

    const float* X    = (const float*)d_in[0];
    const int*   EI   = (const int*)  d_in[iEI];
    const float* t1w1 = (const float*)d_in[iT1W1];
    const float* t1b1 = (const float*)d_in[iT1B1];
    const float* t1w2 = (const float*)d_in[iT1W2];
    const float* t1b2 = (const float*)d_in[iT1B2];
    const float* t1w3 = (const float*)d_in[iT1W3];
    const float* t1b3 = (const float*)d_in[iT1B3];
    const float* chw  = (const float*)d_in[iCW];
    const float* chb  = (const float*)d_in[iCB];
    const float* t2w1 = (const float*)d_in[iT2W1];
    const float* t2b1 = (const float*)d_in[iT2B1];
    const float* t2w2 = (const float*)d_in[iT2W2];
    const float* t2b2 = (const float*)d_in[iT2B2];
    const float* t2w3 = (const float*)d_in[iT2W3];
    const float* t2b3 = (const float*)d_in[iT2B3];
    const float* gam  = (const float*)d_in[iGam];
    const float* bet  = (const float*)d_in[iBet];
    const float* c3w  = (const float*)d_in[iC3W];
    const float* c3b  = (const float*)d_in[iC3B];
    const float* f1w  = (const float*)d_in[iF1W];
    const float* f1b  = (const float*)d_in[iF1B];
    float* out = (float*)d_out;

    static const int PROP_SMEM = (2*NN*HH + 2*EE)*4 + (NN+1)*4;
    cudaFuncSetAttribute(prop_fused_kernel,
                         cudaFuncAttributeMaxDynamicSharedMemorySize, PROP_SMEM);

    tconv1_kernel<<<NSL, 128>>>(X, t1w1, t1b1, t1w2, t1b2, t1w3, t1b3);
    edge_prep_kernel<<<NSL, 256>>>(EI);
    prep_w_kernel<<<(192*384 + 255)/256, 256>>>(chw, t2w1, t2w2, t2w3);
    prop_fused_kernel<<<NSL, 256, PROP_SMEM>>>();
    cheb_mma_kernel<<<MCHEB/128, 256>>>(chb);
    tconv2_mma_kernel<<<MT2/128, 256>>>(t2b1, t2b2, t2b3);
    bn_stats_kernel<<<NN, 256>>>(gam, bet);
    swin_kernel<<<dim3(BB, 25), 128>>>();
    pooled_kernel<<<dim3(BB, 8), 256>>>(c3w, c3b);
    fc_kernel<<<dim3(BB, 25), 128>>>(f1w, f1b, out);
}

// round 5
// speedup vs baseline: 2.8087x; 1.5014x over previous
#include <cuda_runtime.h>
#include <cuda_bf16.h>
#include <math.h>
#include <stdint.h>

// ---------------- problem constants ----------------
#define BB   32
#define TW   40
#define T1   38
#define T2T  36
#define NN   50
#define CIN  2
#define HH   128
#define CO   64
#define EE   800
#define NSL  (BB*T1)        // 1216
#define MCHEB (NSL*NN)      // 60800
#define MT2   (BB*NN*T2T)   // 57600

// ---------------- scratch ----------------
__device__ float g_T0  [(size_t)NSL*NN*HH];   // exact fp32 (prop input)
__device__ float g_T0r [(size_t)NSL*NN*HH];   // tf32-rounded GEMM operand
__device__ float g_Tx1r[(size_t)NSL*NN*HH];
__device__ float g_Tx2r[(size_t)NSL*NN*HH];
__device__ float g_Gr  [(size_t)NSL*NN*HH];   // relu(cheb out), tf32-rounded
__device__ float2 g_ewc[(size_t)NSL*EE];      // {weight, as_float(col*HH)}
__device__ int   g_eoff[NSL*51];
__device__ float g_T2  [BB*T2T*NN*CO];
__device__ float g_WchebT[128*384];           // [n][k], tf32-rounded
__device__ float g_WcatT [192*384];           // [j][k], j=v*64+co, tf32-rounded
__device__ double g_bnPart[4][NN][2];
__device__ float g_bnA[NN];
__device__ float g_bnC[NN];
__device__ float g_S[BB*3*3200];
__device__ float g_pooled[BB*128];

__device__ __forceinline__ float sigm(float x){ return 1.f/(1.f+__expf(-x)); }
__device__ __forceinline__ float tf32r(float x){
    uint32_t r; asm("cvt.rna.tf32.f32 %0, %1;" : "=r"(r) : "f"(x));
    return __uint_as_float(r);
}

// ---------------- PTX helpers (sm_103 baseline only) ----------------
__device__ __forceinline__ uint32_t smem_u32(const void* p){
    uint32_t a;
    asm("{ .reg .u64 t; cvta.to.shared.u64 t, %1; cvt.u32.u64 %0, t; }" : "=r"(a) : "l"(p));
    return a;
}
__device__ __forceinline__ uint32_t swz128(uint32_t off){ return off ^ ((off >> 3) & 0x70); }
__device__ __forceinline__ void cp16(uint32_t dst, const void* src){
    asm volatile("cp.async.cg.shared.global [%0], [%1], 16;" :: "r"(dst), "l"(src));
}
__device__ __forceinline__ void mma_tf32(float* c, const uint32_t* a, const uint32_t* b){
    asm volatile("mma.sync.aligned.m16n8k8.row.col.f32.tf32.tf32.f32 "
        "{%0,%1,%2,%3}, {%4,%5,%6,%7}, {%8,%9}, {%0,%1,%2,%3};"
        : "+f"(c[0]), "+f"(c[1]), "+f"(c[2]), "+f"(c[3])
        : "r"(a[0]),"r"(a[1]),"r"(a[2]),"r"(a[3]), "r"(b[0]),"r"(b[1]));
}
// swizzled word index within a [rows][32-float] tile (128B rows)
__device__ __forceinline__ uint32_t swzw(int row, int k){
    return swz128((uint32_t)(row*128 + k*4)) >> 2;
}

// ---------------- K1: temporal gated conv 1 ----------------
__global__ void tconv1_kernel(const float* __restrict__ X,
                              const float* __restrict__ w1, const float* __restrict__ b1,
                              const float* __restrict__ w2, const float* __restrict__ b2,
                              const float* __restrict__ w3, const float* __restrict__ b3)
{
    int s = blockIdx.x;
    int b = s / T1, t = s % T1;
    int h = threadIdx.x;
    float W1[6], W2[6], W3[6];
#pragma unroll
    for (int i = 0; i < 6; i++) {
        W1[i] = w1[i*128 + h]; W2[i] = w2[i*128 + h]; W3[i] = w3[i*128 + h];
    }
    float bb1 = b1[h], bb2 = b2[h], bb3 = b3[h];

    __shared__ float xs[3][NN*CIN];
    for (int i = threadIdx.x; i < 3*NN*CIN; i += 128) {
        int kt = i / (NN*CIN), rem = i % (NN*CIN);
        xs[kt][rem] = X[((size_t)(b*TW + t + kt)*NN)*CIN + rem];
    }
    __syncthreads();

    size_t ob = ((size_t)s*NN)*HH + h;
    for (int n = 0; n < NN; n++) {
        float p = bb1, q = bb2, r = bb3;
#pragma unroll
        for (int kt = 0; kt < 3; kt++)
#pragma unroll
            for (int c = 0; c < 2; c++) {
                float xv = xs[kt][n*2 + c];
                p += xv * W1[kt*2 + c]; q += xv * W2[kt*2 + c]; r += xv * W3[kt*2 + c];
            }
        float v = p * sigm(q) + r;
        v = v > 0.f ? v : 0.f;
        g_T0 [ob + (size_t)n*HH] = v;
        g_T0r[ob + (size_t)n*HH] = tf32r(v);
    }
}

// -------- K2: edge prep (CSR counting sort; {w, col*HH} interleaved) --------
__global__ void edge_prep_kernel(const int* __restrict__ ei)
{
    int s = blockIdx.x;
    int b = s / T1, t = s % T1;
    const int* row = ei + (size_t)(b*TW + t) * (2*EE);
    const int* col = row + EE;

    __shared__ int   deg[NN];
    __shared__ float dis[NN];
    __shared__ int   off[NN+1];
    __shared__ int   cur[NN];
    __shared__ int   rsh[EE];
    __shared__ int   csh[EE];

    for (int i = threadIdx.x; i < NN; i += blockDim.x) deg[i] = 0;
    __syncthreads();
    for (int e = threadIdx.x; e < EE; e += blockDim.x) {
        int r = row[e];
        rsh[e] = r; csh[e] = col[e];
        atomicAdd(&deg[r], 1);
    }
    __syncthreads();
    if (threadIdx.x == 0) {
        int acc = 0;
        for (int n = 0; n < NN; n++) { off[n] = acc; cur[n] = acc; acc += deg[n]; }
        off[NN] = acc;
    }
    for (int i = threadIdx.x; i < NN; i += blockDim.x)
        dis[i] = deg[i] > 0 ? rsqrtf((float)deg[i]) : 0.f;
    __syncthreads();
    for (int e = threadIdx.x; e < EE; e += blockDim.x) {
        int r = rsh[e], c = csh[e];
        int pos = atomicAdd(&cur[r], 1);
        g_ewc[(size_t)s*EE + pos] = make_float2(-dis[r]*dis[c],
                                                __int_as_float(c * HH));
    }
    for (int i = threadIdx.x; i < NN+1; i += blockDim.x)
        g_eoff[s*(NN+1) + i] = off[i];
}

// -------- K3: fused Chebyshev propagation, float4-vectorized --------
// 256 threads = 8 warps; warp w handles rows n = w, w+8, ...; lane covers f = lane*4..+3
// dyn smem: xs[6400] | xt[6400] | wc[800]x2 | offs[51]
__global__ void prop_fused_kernel()
{
    extern __shared__ __align__(16) float dyn[];
    float*  xs = dyn;                        // 6400
    float*  xt = dyn + NN*HH;                // 6400
    float2* wc = (float2*)(dyn + 2*NN*HH);   // 800 float2
    int*  offs = (int*)(dyn + 2*NN*HH + 2*EE);

    int s = blockIdx.x;
    int tid = threadIdx.x;
    int w = tid >> 5, lane = tid & 31;
    int fb = lane * 4;

    const float4* xsrc = (const float4*)(g_T0 + (size_t)s*NN*HH);
    float4* xs4 = (float4*)xs;
    for (int i = tid; i < NN*HH/4; i += 256) xs4[i] = xsrc[i];
    const float2* wsrc = g_ewc + (size_t)s*EE;
    for (int e = tid; e < EE; e += 256) wc[e] = wsrc[e];
    if (tid < NN+1) offs[tid] = g_eoff[s*(NN+1) + tid];
    __syncthreads();

    // phase 1: Tx1 = L~ @ T0
    for (int n = w; n < NN; n += 8) {
        int e0 = offs[n], e1 = offs[n+1];
        float4 acc = make_float4(0.f, 0.f, 0.f, 0.f);
#pragma unroll 4
        for (int e = e0; e < e1; e++) {
            float2 p = wc[e];
            const float4 xv = *(const float4*)(xs + __float_as_int(p.y) + fb);
            acc.x += p.x*xv.x; acc.y += p.x*xv.y; acc.z += p.x*xv.z; acc.w += p.x*xv.w;
        }
        *(float4*)(xt + n*HH + fb) = acc;
        *(float4*)(&g_Tx1r[((size_t)s*NN + n)*HH + fb]) =
            make_float4(tf32r(acc.x), tf32r(acc.y), tf32r(acc.z), tf32r(acc.w));
    }
    __syncthreads();
    // phase 2: Tx2 = 2 L~ @ Tx1 - T0
    for (int n = w; n < NN; n += 8) {
        int e0 = offs[n], e1 = offs[n+1];
        float4 acc = make_float4(0.f, 0.f, 0.f, 0.f);
#pragma unroll 4
        for (int e = e0; e < e1; e++) {
            float2 p = wc[e];
            const float4 xv = *(const float4*)(xt + __float_as_int(p.y) + fb);
            acc.x += p.x*xv.x; acc.y += p.x*xv.y; acc.z += p.x*xv.z; acc.w += p.x*xv.w;
        }
        const float4 x0 = *(const float4*)(xs + n*HH + fb);
        *(float4*)(&g_Tx2r[((size_t)s*NN + n)*HH + fb]) =
            make_float4(tf32r(2.f*acc.x - x0.x), tf32r(2.f*acc.y - x0.y),
                        tf32r(2.f*acc.z - x0.z), tf32r(2.f*acc.w - x0.w));
    }
}

// -------- K3b: weight prep (transpose + tf32 round) --------
__global__ void prep_w_kernel(const float* __restrict__ chw,
                              const float* __restrict__ w1,
                              const float* __restrict__ w2,
                              const float* __restrict__ w3)
{
    int idx = blockIdx.x*256 + threadIdx.x;
    if (idx < 128*384) {
        int n = idx / 384, k = idx % 384;
        g_WchebT[idx] = tf32r(chw[k*128 + n]);
    }
    if (idx < 192*384) {
        int j = idx / 384, k = idx % 384;
        int v = j >> 6, co = j & 63;
        const float* w = (v == 0) ? w1 : (v == 1 ? w2 : w3);
        g_WcatT[idx] = tf32r(w[k*64 + co]);
    }
}

// -------- K4: cheb einsum GEMM, tf32 mma, 2-stage cp.async pipeline --------
__global__ __launch_bounds__(256, 1)
void cheb_mma_kernel(const float* __restrict__ bias)
{
    extern __shared__ __align__(1024) float dynS[];   // 2 stages x (A 4096 + B 4096)

    int tid = threadIdx.x;
    int wid = tid >> 5, lane = tid & 31;
    int wm = (wid >> 2) * 64;
    int wn = (wid & 3) * 32;
    size_t m0 = (size_t)blockIdx.x * 128;

    float acc[4][4][4];
#pragma unroll
    for (int i = 0; i < 4; i++)
#pragma unroll
        for (int j = 0; j < 4; j++)
#pragma unroll
            for (int r = 0; r < 4; r++) acc[i][j][r] = 0.f;

    auto issue = [&](int c, int stage){
        float* sAf = dynS + stage*8192;
        float* sBf = sAf + 4096;
        uint32_t sa = smem_u32(sAf), sb = smem_u32(sBf);
        const float* Am = (c < 4) ? g_T0r : (c < 8 ? g_Tx1r : g_Tx2r);
        int k0 = (c & 3) * 32;
#pragma unroll
        for (int i = 0; i < 4; i++) {
            int u = tid + i*256;
            int row = u >> 3, un = u & 7;
            cp16(sa + swz128((uint32_t)(row*128 + un*16)),
                 Am + (m0 + row)*HH + k0 + un*4);
        }
#pragma unroll
        for (int i = 0; i < 4; i++) {
            int u = tid + i*256;
            int row = u >> 3, un = u & 7;
            cp16(sb + swz128((uint32_t)(row*128 + un*16)),
                 g_WchebT + (size_t)row*384 + c*32 + un*4);
        }
        asm volatile("cp.async.commit_group;");
    };

    issue(0, 0);
    for (int c = 0; c < 12; c++) {
        if (c < 11) {
            issue(c+1, (c+1)&1);
            asm volatile("cp.async.wait_group 1;");
        } else {
            asm volatile("cp.async.wait_group 0;");
        }
        __syncthreads();
        const uint32_t* sAu = (const uint32_t*)(dynS + (c&1)*8192);
        const uint32_t* sBu = sAu + 4096;

#pragma unroll
        for (int k8 = 0; k8 < 4; k8++) {
            int kb = k8*8 + (lane & 3);
            uint32_t a[4][4], b[4][2];
#pragma unroll
            for (int mf = 0; mf < 4; mf++) {
                int r0 = wm + mf*16 + (lane >> 2);
                a[mf][0] = sAu[swzw(r0,     kb)];
                a[mf][1] = sAu[swzw(r0 + 8, kb)];
                a[mf][2] = sAu[swzw(r0,     kb + 4)];
                a[mf][3] = sAu[swzw(r0 + 8, kb + 4)];
            }
#pragma unroll
            for (int nf = 0; nf < 4; nf++) {
                int n0 = wn + nf*8 + (lane >> 2);
                b[nf][0] = sBu[swzw(n0, kb)];
                b[nf][1] = sBu[swzw(n0, kb + 4)];
            }
#pragma unroll
            for (int mf = 0; mf < 4; mf++)
#pragma unroll
                for (int nf = 0; nf < 4; nf++)
                    mma_tf32(acc[mf][nf], a[mf], b[nf]);
        }
        __syncthreads();
    }

    int rl = lane >> 2, cl = (lane & 3)*2;
#pragma unroll
    for (int mf = 0; mf < 4; mf++) {
        size_t mrow = m0 + wm + mf*16 + rl;
#pragma unroll
        for (int nf = 0; nf < 4; nf++) {
            int n = wn + nf*8 + cl;
            float bv0 = bias[n], bv1 = bias[n+1];
            float v00 = acc[mf][nf][0] + bv0; v00 = v00 > 0.f ? v00 : 0.f;
            float v01 = acc[mf][nf][1] + bv1; v01 = v01 > 0.f ? v01 : 0.f;
            float v10 = acc[mf][nf][2] + bv0; v10 = v10 > 0.f ? v10 : 0.f;
            float v11 = acc[mf][nf][3] + bv1; v11 = v11 > 0.f ? v11 : 0.f;
            *reinterpret_cast<float2*>(&g_Gr[mrow*HH + n]) =
                make_float2(tf32r(v00), tf32r(v01));
            *reinterpret_cast<float2*>(&g_Gr[(mrow+8)*HH + n]) =
                make_float2(tf32r(v10), tf32r(v11));
        }
    }
}

// -------- K5: tconv2 GEMM, tf32 mma, 2-stage pipeline + gated epilogue --------
__global__ __launch_bounds__(256, 1)
void tconv2_mma_kernel(const float* __restrict__ b1,
                       const float* __restrict__ b2,
                       const float* __restrict__ b3)
{
    extern __shared__ __align__(1024) float dynS[];   // 2 stages x (A 4096 + B 6144)

    int tid = threadIdx.x;
    int wid = tid >> 5, lane = tid & 31;
    int wm = (wid >> 2) * 64;
    int cg = wid & 3;
    int m0 = blockIdx.x * 128;

    float acc[4][3][2][4];
#pragma unroll
    for (int i = 0; i < 4; i++)
#pragma unroll
        for (int v = 0; v < 3; v++)
#pragma unroll
            for (int cf = 0; cf < 2; cf++)
#pragma unroll
                for (int r = 0; r < 4; r++) acc[i][v][cf][r] = 0.f;

    auto issue = [&](int c, int stage){
        float* sAf = dynS + stage*10240;
        float* sBf = sAf + 4096;
        uint32_t sa = smem_u32(sAf), sb = smem_u32(sBf);
        int kt = c >> 2;
        int k0 = (c & 3) * 32;
#pragma unroll
        for (int i = 0; i < 4; i++) {
            int u = tid + i*256;
            int row = u >> 3, un = u & 7;
            int gm = m0 + row;
            int t = gm % 36, n = (gm/36) % 50, b = gm / 1800;
            cp16(sa + swz128((uint32_t)(row*128 + un*16)),
                 g_Gr + (((size_t)(b*T1 + t + kt))*NN + n)*HH + k0 + un*4);
        }
#pragma unroll
        for (int i = 0; i < 6; i++) {
            int u = tid + i*256;
            int row = u >> 3, un = u & 7;
            cp16(sb + swz128((uint32_t)(row*128 + un*16)),
                 g_WcatT + (size_t)row*384 + c*32 + un*4);
        }
        asm volatile("cp.async.commit_group;");
    };

    issue(0, 0);
    for (int c = 0; c < 12; c++) {
        if (c < 11) {
            issue(c+1, (c+1)&1);
            asm volatile("cp.async.wait_group 1;");
        } else {
            asm volatile("cp.async.wait_group 0;");
        }
        __syncthreads();
        const uint32_t* sAu = (const uint32_t*)(dynS + (c&1)*10240);
        const uint32_t* sBu = sAu + 4096;

#pragma unroll
        for (int k8 = 0; k8 < 4; k8++) {
            int kb = k8*8 + (lane & 3);
            uint32_t a[4][4], b[6][2];
#pragma unroll
            for (int mf = 0; mf < 4; mf++) {
                int r0 = wm + mf*16 + (lane >> 2);
                a[mf][0] = sAu[swzw(r0,     kb)];
                a[mf][1] = sAu[swzw(r0 + 8, kb)];
                a[mf][2] = sAu[swzw(r0,     kb + 4)];
                a[mf][3] = sAu[swzw(r0 + 8, kb + 4)];
            }
#pragma unroll
            for (int v = 0; v < 3; v++)
#pragma unroll
                for (int cf = 0; cf < 2; cf++) {
                    int nrow = v*64 + cg*16 + cf*8 + (lane >> 2);
                    b[v*2+cf][0] = sBu[swzw(nrow, kb)];
                    b[v*2+cf][1] = sBu[swzw(nrow, kb + 4)];
                }
#pragma unroll
            for (int mf = 0; mf < 4; mf++)
#pragma unroll
                for (int v = 0; v < 3; v++)
#pragma unroll
                    for (int cf = 0; cf < 2; cf++)
                        mma_tf32(acc[mf][v][cf], a[mf], b[v*2+cf]);
        }
        __syncthreads();
    }

    int rl = lane >> 2, cl = (lane & 3)*2;
#pragma unroll
    for (int mf = 0; mf < 4; mf++) {
#pragma unroll
        for (int h = 0; h < 2; h++) {
            int gm = m0 + wm + mf*16 + rl + h*8;
            int t = gm % 36, n = (gm/36) % 50, b = gm / 1800;
            float* dst = g_T2 + (((size_t)(b*T2T + t))*NN + n)*CO;
#pragma unroll
            for (int cf = 0; cf < 2; cf++) {
                int co = cg*16 + cf*8 + cl;
                float p0 = acc[mf][0][cf][h*2+0] + b1[co];
                float p1 = acc[mf][0][cf][h*2+1] + b1[co+1];
                float q0 = acc[mf][1][cf][h*2+0] + b2[co];
                float q1 = acc[mf][1][cf][h*2+1] + b2[co+1];
                float r0 = acc[mf][2][cf][h*2+0] + b3[co];
                float r1 = acc[mf][2][cf][h*2+1] + b3[co+1];
                float v0 = p0 * sigm(q0) + r0; v0 = v0 > 0.f ? v0 : 0.f;
                float v1 = p1 * sigm(q1) + r1; v1 = v1 > 0.f ? v1 : 0.f;
                *reinterpret_cast<float2*>(dst + co) = make_float2(v0, v1);
            }
        }
    }
}

// -------- K6a: BN partial sums (grid NN x 4, deterministic two-stage) --------
__global__ void bn_part_kernel()
{
    int n = blockIdx.x, q = blockIdx.y;
    int tid = threadIdx.x;
    const int CH = BB*T2T/4;   // 288 bt per part
    double s = 0.0, s2 = 0.0;
    for (int i = tid; i < CH*CO; i += 256) {
        int bt = q*CH + (i >> 6), co = i & 63;
        float v = g_T2[((size_t)bt*NN + n)*CO + co];
        s += v; s2 += (double)v*v;
    }
    __shared__ double shs[256], shs2[256];
    shs[tid] = s; shs2[tid] = s2;
    __syncthreads();
    for (int stp = 128; stp > 0; stp >>= 1) {
        if (tid < stp) { shs[tid] += shs[tid+stp]; shs2[tid] += shs2[tid+stp]; }
        __syncthreads();
    }
    if (tid == 0) { g_bnPart[q][n][0] = shs[0]; g_bnPart[q][n][1] = shs2[0]; }
}

// -------- K6b: BN finalize --------
__global__ void bn_final_kernel(const float* __restrict__ gamma,
                                const float* __restrict__ beta)
{
    int n = threadIdx.x;
    if (n < NN) {
        double s = 0.0, s2 = 0.0;
#pragma unroll
        for (int q = 0; q < 4; q++) { s += g_bnPart[q][n][0]; s2 += g_bnPart[q][n][1]; }
        const double M = (double)(BB*T2T*CO);
        double mean = s / M;
        double var  = s2 / M - mean*mean;
        float rstd = (float)(1.0 / sqrt(var + 1e-5));
        float a = rstd * gamma[n];
        g_bnA[n] = a;
        g_bnC[n] = beta[n] - (float)mean * a;
    }
}

// -------- K7: window sums with BN folded --------
__global__ void swin_kernel()
{
    int b = blockIdx.x;
    int j = blockIdx.y*128 + threadIdx.x;
    const float* base = g_T2 + (size_t)b*T2T*3200 + j;
    float tot = 0.f, v0 = 0.f, v1 = 0.f, v34 = 0.f, v35 = 0.f;
#pragma unroll
    for (int t = 0; t < T2T; t++) {
        float v = base[(size_t)t*3200];
        tot += v;
        if (t == 0)  v0  = v;
        if (t == 1)  v1  = v;
        if (t == 34) v34 = v;
        if (t == 35) v35 = v;
    }
    int n = j >> 6;
    float a = g_bnA[n], c = 34.f * g_bnC[n];
    g_S[((size_t)b*3 + 0)*3200 + j] = a*(tot - v34 - v35) + c;
    g_S[((size_t)b*3 + 1)*3200 + j] = a*(tot - v0  - v35) + c;
    g_S[((size_t)b*3 + 2)*3200 + j] = a*(tot - v0  - v1 ) + c;
}

// -------- K8: pooled --------
__global__ void pooled_kernel(const float* __restrict__ w,
                              const float* __restrict__ cb)
{
    int b  = blockIdx.x;
    int og = blockIdx.y;
    __shared__ float sS[9600];
    for (int i = threadIdx.x; i < 9600; i += 256)
        sS[i] = g_S[(size_t)b*9600 + i];
    __syncthreads();
    int warp = threadIdx.x >> 5, lane = threadIdx.x & 31;
    for (int oi = warp; oi < 16; oi += 8) {
        int o = og*16 + oi;
        const float* wr = w + (size_t)o*9600;
        float acc = 0.f;
        for (int jj = lane; jj < 9600; jj += 32)
            acc += wr[jj] * sS[jj];
#pragma unroll
        for (int d = 16; d > 0; d >>= 1)
            acc += __shfl_down_sync(0xffffffffu, acc, d);
        if (lane == 0)
            g_pooled[b*128 + o] = acc * (1.f/34.f) + cb[o];
    }
}

// -------- K9: fc --------
__global__ void fc_kernel(const float* __restrict__ f1w,
                          const float* __restrict__ f1b,
                          float* __restrict__ out)
{
    int b = blockIdx.x;
    int q = blockIdx.y*128 + threadIdx.x;
    __shared__ float p[128];
    p[threadIdx.x] = g_pooled[b*128 + threadIdx.x];
    __syncthreads();
    float acc = f1b[q];
#pragma unroll 8
    for (int o = 0; o < 128; o++)
        acc += p[o] * f1w[(size_t)o*3200 + q];
    out[(size_t)b*3200 + q] = acc;
}

// ---------------- launch ----------------
extern "C" void kernel_launch(void* const* d_in, const int* in_sizes, int n_in,
                              void* d_out, int out_size)
{
    int iEI, iT1W1, iT1B1, iT1W2, iT1B2, iT1W3, iT1B3, iCW, iCB;
    int iT2W1, iT2B1, iT2W2, iT2B2, iT2W3, iT2B3, iGam, iBet, iC3W, iC3B, iF1W, iF1B;
    if (n_in > 1 && in_sizes[1] == BB*TW*2*EE) {
        iEI=1;  iT1W1=2;  iT1B1=3;  iT1W2=4;  iT1B2=5;  iT1W3=6;  iT1B3=7;
        iCW=8;  iCB=9;
        iT2W1=10; iT2B1=11; iT2W2=12; iT2B2=13; iT2W3=14; iT2B3=15;
        iGam=16; iBet=17; iC3W=18; iC3B=19; iF1W=20; iF1B=21;
    } else {
        iT1W1=1;  iT1B1=2;  iT1W2=3;  iT1B2=4;  iT1W3=5;  iT1B3=6;
        iCW=7;  iCB=8;
        iT2W1=9;  iT2B1=10; iT2W2=11; iT2B2=12; iT2W3=13; iT2B3=14;
        iGam=15; iBet=16; iC3W=17; iC3B=18; iF1W=19; iF1B=20; iEI=21;
    }

    const float* X    = (const float*)d_in[0];
    const int*   EI   = (const int*)  d_in[iEI];
    const float* t1w1 = (const float*)d_in[iT1W1];
    const float* t1b1 = (const float*)d_in[iT1B1];
    const float* t1w2 = (const float*)d_in[iT1W2];
    const float* t1b2 = (const float*)d_in[iT1B2];
    const float* t1w3 = (const float*)d_in[iT1W3];
    const float* t1b3 = (const float*)d_in[iT1B3];
    const float* chw  = (const float*)d_in[iCW];
    const float* chb  = (const float*)d_in[iCB];
    const float* t2w1 = (const float*)d_in[iT2W1];
    const float* t2b1 = (const float*)d_in[iT2B1];
    const float* t2w2 = (const float*)d_in[iT2W2];
    const float* t2b2 = (const float*)d_in[iT2B2];
    const float* t2w3 = (const float*)d_in[iT2W3];
    const float* t2b3 = (const float*)d_in[iT2B3];
    const float* gam  = (const float*)d_in[iGam];
    const float* bet  = (const float*)d_in[iBet];
    const float* c3w  = (const float*)d_in[iC3W];
    const float* c3b  = (const float*)d_in[iC3B];
    const float* f1w  = (const float*)d_in[iF1W];
    const float* f1b  = (const float*)d_in[iF1B];
    float* out = (float*)d_out;

    static const int PROP_SMEM  = (2*NN*HH + 2*EE)*4 + (NN+1)*4;   // 57,804 B
    static const int CHEB_SMEM  = 2*8192*4;                         // 65,536 B
    static const int T2_SMEM    = 2*10240*4;                        // 81,920 B
    cudaFuncSetAttribute(prop_fused_kernel,
                         cudaFuncAttributeMaxDynamicSharedMemorySize, PROP_SMEM);
    cudaFuncSetAttribute(cheb_mma_kernel,
                         cudaFuncAttributeMaxDynamicSharedMemorySize, CHEB_SMEM);
    cudaFuncSetAttribute(tconv2_mma_kernel,
                         cudaFuncAttributeMaxDynamicSharedMemorySize, T2_SMEM);

    tconv1_kernel<<<NSL, 128>>>(X, t1w1, t1b1, t1w2, t1b2, t1w3, t1b3);
    edge_prep_kernel<<<NSL, 256>>>(EI);
    prep_w_kernel<<<(192*384 + 255)/256, 256>>>(chw, t2w1, t2w2, t2w3);
    prop_fused_kernel<<<NSL, 256, PROP_SMEM>>>();
    cheb_mma_kernel<<<MCHEB/128, 256, CHEB_SMEM>>>(chb);
    tconv2_mma_kernel<<<MT2/128, 256, T2_SMEM>>>(t2b1, t2b2, t2b3);
    bn_part_kernel<<<dim3(NN, 4), 256>>>();
    bn_final_kernel<<<1, 64>>>(gam, bet);
    swin_kernel<<<dim3(BB, 25), 128>>>();
    pooled_kernel<<<dim3(BB, 8), 256>>>(c3w, c3b);
    fc_kernel<<<dim3(BB, 25), 128>>>(f1w, f1b, out);
}